// round 16
// baseline (speedup 1.0000x reference)
#include <cuda_runtime.h>
#include <cuda_bf16.h>
#include <cstdint>

// ============================================================================
// Problem constants
// ============================================================================
#define BATCH   8192
#define NFEAT   512
#define NLEAF   1024
#define ATOMS   513          // 1 + NFEAT

// GEMM tiling (mma.sync m16n8k16 bf16 path — family-common, no tcgen05)
#define MT      128          // CTA M-tile
#define NT      128          // CTA N-tile
#define KT      64           // K per smem stage (128 bytes/row, SW128 atom)
#define NKT     (NFEAT / KT) // 8 K-tiles
#define NTILES  (NLEAF / NT) // 8 N-tiles (grid.y)
#define STAGES  3

// Dynamic smem layout
#define STAGE_BYTES 16384                    // 128 rows x 128 bytes
#define SM_A        0                        // 3 stages
#define SM_B        (STAGES * STAGE_BYTES)   // 49152
#define SM_BIAS     (2 * STAGES * STAGE_BYTES)  // 98304, 128 f32
#define SM_RS       (SM_BIAS + 512)          // 98816, 128 x 2 f32
#define SMEM_TOTAL  (SM_RS + 1024)           // 99840

#define CVT_BLOCKS  2048                     // convert blocks (4 loads each)

// ============================================================================
// Scratch (static device globals — no runtime allocation)
// ============================================================================
__device__ __nv_bfloat16 g_Xbf[BATCH * NFEAT];      // 8 MB
__device__ __nv_bfloat16 g_Wbf[NLEAF * NFEAT];      // 1 MB
__device__ float         g_bias[NLEAF];
__device__ float         g_part[BATCH * NTILES];    // row-major: [row][tile]

// ============================================================================
// Helpers
// ============================================================================
__device__ __forceinline__ uint32_t smem_to_u32(const void* p) {
    uint32_t a;
    asm("{ .reg .u64 t; cvta.to.shared.u64 t, %1; cvt.u32.u64 %0, t; }"
        : "=r"(a) : "l"(p));
    return a;
}

#define SMEM_SWIZZLE_128B(off) ((off) ^ (((off) >> 3) & 0x70))

__device__ __forceinline__ void cp_async16(uint32_t dst, const void* src) {
    asm volatile("cp.async.cg.shared.global [%0], [%1], 16;"
                 :: "r"(dst), "l"(src) : "memory");
}
#define CP_COMMIT() asm volatile("cp.async.commit_group;" ::: "memory")
#define CP_WAIT(n)  asm volatile("cp.async.wait_group %0;" :: "n"(n) : "memory")

__device__ __forceinline__ void ldm_x4(uint32_t* r, uint32_t addr) {
    asm volatile("ldmatrix.sync.aligned.m8n8.x4.shared.b16 {%0,%1,%2,%3}, [%4];"
        : "=r"(r[0]), "=r"(r[1]), "=r"(r[2]), "=r"(r[3]) : "r"(addr));
}

__device__ __forceinline__ void mma_bf16(float* c, const uint32_t* a, const uint32_t* b) {
    asm volatile(
        "mma.sync.aligned.m16n8k16.row.col.f32.bf16.bf16.f32 "
        "{%0,%1,%2,%3}, {%4,%5,%6,%7}, {%8,%9}, {%0,%1,%2,%3};"
        : "+f"(c[0]), "+f"(c[1]), "+f"(c[2]), "+f"(c[3])
        : "r"(a[0]), "r"(a[1]), "r"(a[2]), "r"(a[3]), "r"(b[0]), "r"(b[1]));
}

__device__ __forceinline__ uint2 cvt_f4_bf4(float4 v) {
    __nv_bfloat162 lo = __floats2bfloat162_rn(v.x, v.y);
    __nv_bfloat162 hi = __floats2bfloat162_rn(v.z, v.w);
    uint2 u;
    u.x = *reinterpret_cast<unsigned int*>(&lo);
    u.y = *reinterpret_cast<unsigned int*>(&hi);
    return u;
}

// ============================================================================
// Kernel 0 (merged): blocks [0,1024)      = per-leaf softmax (row in regs)
//                    blocks [1024,3072)   = X fp32 -> bf16 convert (MLP=4)
// Measured-best prep shape (R13 bench: wall 35.33us, prep regs=30, occ 76%).
// ============================================================================
__global__ void __launch_bounds__(128) prep_kernel(const float* __restrict__ X,
                                                   const float* __restrict__ logits) {
    const int bid = blockIdx.x;
    const int tid = threadIdx.x;

    if (bid >= NLEAF) {
        const int cb = bid - NLEAF;                   // 0..2047
        const float4* x4 = (const float4*)X;
        uint2* o = (uint2*)g_Xbf;
        const int base = cb * 128 + tid;              // 0..262143
        const int S = CVT_BLOCKS * 128;               // 262144 (n4 = 1048576)
        // ---- 4 independent loads, all issued before first use ----
        float4 v0 = __ldcs(&x4[base]);
        float4 v1 = __ldcs(&x4[base + S]);
        float4 v2 = __ldcs(&x4[base + 2 * S]);
        float4 v3 = __ldcs(&x4[base + 3 * S]);
        __stcs(&o[base],         cvt_f4_bf4(v0));
        __stcs(&o[base + S],     cvt_f4_bf4(v1));
        __stcs(&o[base + 2 * S], cvt_f4_bf4(v2));
        __stcs(&o[base + 3 * S], cvt_f4_bf4(v3));
        return;
    }

    // ---- softmax over 513 atoms for leaf `bid`, row cached in registers ----
    const int l = bid;
    const float* row = logits + (size_t)l * ATOMS;
    __shared__ float red_m[4];
    __shared__ float red_s[4];

    float v[4];
    #pragma unroll
    for (int j = 0; j < 4; j++) v[j] = row[tid + j * 128];   // 0..511
    const float vx = (tid == 0) ? row[512] : -1e30f;          // atom 512

    float m = fmaxf(fmaxf(v[0], v[1]), fmaxf(v[2], v[3]));
    m = fmaxf(m, vx);
    #pragma unroll
    for (int o = 16; o; o >>= 1) m = fmaxf(m, __shfl_xor_sync(~0u, m, o));
    if ((tid & 31) == 0) red_m[tid >> 5] = m;
    __syncthreads();
    m = fmaxf(fmaxf(red_m[0], red_m[1]), fmaxf(red_m[2], red_m[3]));

    float e[4];
    float s = 0.f;
    #pragma unroll
    for (int j = 0; j < 4; j++) { e[j] = __expf(v[j] - m); s += e[j]; }
    const float ex = (tid == 0) ? __expf(vx - m) : 0.f;
    s += ex;
    #pragma unroll
    for (int o = 16; o; o >>= 1) s += __shfl_xor_sync(~0u, s, o);
    if ((tid & 31) == 0) red_s[tid >> 5] = s;
    __syncthreads();
    s = red_s[0] + red_s[1] + red_s[2] + red_s[3];
    const float inv = 1.0f / s;

    __nv_bfloat16* W = g_Wbf + (size_t)l * NFEAT;
    #pragma unroll
    for (int j = 0; j < 4; j++) {
        const int k = tid + j * 128;
        const float w = e[j] * inv;
        if (k == 0) g_bias[l] = w;
        else        W[k - 1] = __float2bfloat16(w);
    }
    if (tid == 0) W[511] = __float2bfloat16(ex * inv);        // atom 512
}

// ============================================================================
// Kernel 1: bf16 mma.sync GEMM 128x128xK512, 3-stage cp.async pipeline,
//           fused bias + exp + row sum-exp
// grid = (BATCH/128, NLEAF/128), 256 threads (8 warps as 4 x 2)
// Inner loop = measured-best per-p form. DO NOT perturb: batched b[4][4] was
// neutral (R14), ping-pong double-buffer regressed 45% (R15, reg-cap spill).
// ============================================================================
__global__ void __launch_bounds__(256, 2) gemm_lse_kernel() {
    extern __shared__ __align__(16) char smem[];
    uint32_t sb = smem_to_u32(smem);
    const int tid = threadIdx.x;
    const int lid = tid & 31;
    const int wid = tid >> 5;
    const int warpM = wid >> 1;     // 0..3  (32 rows each)
    const int warpN = wid & 1;      // 0..1  (64 cols each)
    const int m0 = blockIdx.x * MT;
    const int n0 = blockIdx.y * NT;

    float* bias_s = (float*)(smem + SM_BIAS);
    float* rs     = (float*)(smem + SM_RS);
    for (int i = tid; i < NT; i += 256) bias_s[i] = g_bias[n0 + i];

    const char* Asrc = (const char*)(g_Xbf + (size_t)m0 * NFEAT);
    const char* Bsrc = (const char*)(g_Wbf + (size_t)n0 * NFEAT);

    auto load_tile = [&](int kt, int stage) {
        uint32_t abase = sb + SM_A + stage * STAGE_BYTES;
        uint32_t bbase = sb + SM_B + stage * STAGE_BYTES;
        #pragma unroll
        for (int i = 0; i < 4; i++) {
            int idx = tid + i * 256;         // 0..1023
            int row = idx >> 3, j = idx & 7;
            uint32_t sw = SMEM_SWIZZLE_128B((uint32_t)(row * 128 + j * 16));
            const size_t gsrc = ((size_t)row * NFEAT + (size_t)kt * KT) * 2 + j * 16;
            cp_async16(abase + sw, Asrc + gsrc);
            cp_async16(bbase + sw, Bsrc + gsrc);
        }
    };

    // ldmatrix per-lane pre-swizzle byte offsets
    const uint32_t a_off0 = (uint32_t)((warpM * 32 +  0 + (lid & 15)) * 128 + ((lid >> 4) << 4));
    const uint32_t a_off1 = (uint32_t)((warpM * 32 + 16 + (lid & 15)) * 128 + ((lid >> 4) << 4));
    const int b_nrow = (lid & 7) + ((lid >> 4) << 3);
    const uint32_t b_off = (uint32_t)((warpN * 64 + b_nrow) * 128 + (((lid >> 3) & 1) << 4));

    float acc[2][8][4];
    #pragma unroll
    for (int m = 0; m < 2; m++)
        #pragma unroll
        for (int nf = 0; nf < 8; nf++)
            #pragma unroll
            for (int c = 0; c < 4; c++) acc[m][nf][c] = 0.f;

    // Prologue: stages 0,1 in flight
    load_tile(0, 0);
    CP_COMMIT();
    load_tile(1, 1);
    CP_COMMIT();

    int stage = 0;
    for (int kt = 0; kt < NKT; kt++) {
        CP_WAIT(1);                // stage kt's group complete (groups retire in order)
        __syncthreads();           // visibility + WAR guard for stage (kt+2)%3

        if (kt + 2 < NKT) load_tile(kt + 2, (stage + 2 >= STAGES) ? stage + 2 - STAGES : stage + 2);
        CP_COMMIT();               // exactly one group per iteration (may be empty)

        const uint32_t abase = sb + SM_A + stage * STAGE_BYTES;
        const uint32_t bbase = sb + SM_B + stage * STAGE_BYTES;

        #pragma unroll
        for (int ks = 0; ks < 4; ks++) {     // 4 x k16 = KT
            uint32_t a[2][4];
            ldm_x4(a[0], abase + SMEM_SWIZZLE_128B(a_off0 + ks * 32));
            ldm_x4(a[1], abase + SMEM_SWIZZLE_128B(a_off1 + ks * 32));
            #pragma unroll
            for (int p = 0; p < 4; p++) {    // 4 x (2 n-octets) = 64 cols
                uint32_t b[4];
                ldm_x4(b, bbase + SMEM_SWIZZLE_128B(b_off + p * 2048 + ks * 32));
                mma_bf16(acc[0][2 * p],     a[0], b);
                mma_bf16(acc[0][2 * p + 1], a[0], b + 2);
                mma_bf16(acc[1][2 * p],     a[1], b);
                mma_bf16(acc[1][2 * p + 1], a[1], b + 2);
            }
        }
        stage = (stage + 1 >= STAGES) ? 0 : stage + 1;
    }

    // Fused epilogue: exp(acc + bias), reduce rows deterministically
    const int g  = lid >> 2;
    const int tg = lid & 3;
    #pragma unroll
    for (int m = 0; m < 2; m++) {
        #pragma unroll
        for (int h = 0; h < 2; h++) {        // h=0: rows g, h=1: rows g+8
            float s = 0.f;
            #pragma unroll
            for (int nf = 0; nf < 8; nf++) {
                const int col = warpN * 64 + nf * 8 + tg * 2;
                s += __expf(acc[m][nf][2 * h]     + bias_s[col]);
                s += __expf(acc[m][nf][2 * h + 1] + bias_s[col + 1]);
            }
            s += __shfl_xor_sync(~0u, s, 1);
            s += __shfl_xor_sync(~0u, s, 2);
            if (tg == 0) {
                const int row = warpM * 32 + m * 16 + h * 8 + g;
                rs[row * 2 + warpN] = s;
            }
        }
    }
    __syncthreads();
    if (tid < MT) {
        // row-major partials: [row][tile] -> finalize reads 2 contiguous float4
        g_part[(size_t)(m0 + tid) * NTILES + blockIdx.y] = rs[tid * 2] + rs[tid * 2 + 1];
    }
}

// ============================================================================
// Kernel 2: combine the 8 contiguous per-row partials, final log
// ============================================================================
__global__ void __launch_bounds__(128) finalize_kernel(float* __restrict__ out) {
    int i = blockIdx.x * blockDim.x + threadIdx.x;
    if (i < BATCH) {
        const float4* p = (const float4*)g_part;
        float4 a = p[i * 2];
        float4 b = p[i * 2 + 1];
        out[i] = logf((a.x + a.y + a.z + a.w) + (b.x + b.y + b.z + b.w));
    }
}

// ============================================================================
// Launch
// ============================================================================
extern "C" void kernel_launch(void* const* d_in, const int* in_sizes, int n_in,
                              void* d_out, int out_size) {
    const float* X      = (const float*)d_in[0];   // (8192, 512) f32
    const float* logits = (const float*)d_in[1];   // (1024, 513) f32
    float* out          = (float*)d_out;           // (8192,) f32

    cudaFuncSetAttribute(gemm_lse_kernel,
                         cudaFuncAttributeMaxDynamicSharedMemorySize, SMEM_TOTAL);

    prep_kernel<<<NLEAF + CVT_BLOCKS, 128>>>(X, logits);  // 1024 softmax + 2048 convert
    gemm_lse_kernel<<<dim3(BATCH / MT, NLEAF / NT), 256, SMEM_TOTAL>>>();
    finalize_kernel<<<BATCH / 128, 128>>>(out);
}

// round 17
// speedup vs baseline: 1.4826x; 1.4826x over previous
#include <cuda_runtime.h>
#include <cuda_bf16.h>
#include <cstdint>

// ============================================================================
// Problem constants
// ============================================================================
#define BATCH   8192
#define NFEAT   512
#define NLEAF   1024
#define ATOMS   513          // 1 + NFEAT

// GEMM tiling (mma.sync m16n8k16 bf16 path — family-common, no tcgen05)
#define MT      128          // CTA M-tile
#define NT      128          // CTA N-tile
#define KT      64           // K per smem stage (128 bytes/row, SW128 atom)
#define NKT     (NFEAT / KT) // 8 K-tiles
#define NTILES  (NLEAF / NT) // 8 N-tiles (grid.y)
#define STAGES  3

// Dynamic smem layout
#define STAGE_BYTES 16384                    // 128 rows x 128 bytes
#define SM_A        0                        // 3 stages
#define SM_B        (STAGES * STAGE_BYTES)   // 49152
#define SM_BIAS     (2 * STAGES * STAGE_BYTES)  // 98304, 128 f32
#define SM_RS       (SM_BIAS + 512)          // 98816, 128 x 2 f32
#define SMEM_TOTAL  (SM_RS + 1024)           // 99840

#define CVT_BLOCKS  1024                     // convert blocks (8 loads each)

// ============================================================================
// Scratch (static device globals — no runtime allocation)
// ============================================================================
__device__ __nv_bfloat16 g_Xbf[BATCH * NFEAT];      // 8 MB
__device__ __nv_bfloat16 g_Wbf[NLEAF * NFEAT];      // 1 MB
__device__ float         g_bias[NLEAF];
__device__ float         g_part[BATCH * NTILES];    // row-major: [row][tile]

// ============================================================================
// Helpers
// ============================================================================
__device__ __forceinline__ uint32_t smem_to_u32(const void* p) {
    uint32_t a;
    asm("{ .reg .u64 t; cvta.to.shared.u64 t, %1; cvt.u32.u64 %0, t; }"
        : "=r"(a) : "l"(p));
    return a;
}

#define SMEM_SWIZZLE_128B(off) ((off) ^ (((off) >> 3) & 0x70))

__device__ __forceinline__ void cp_async16(uint32_t dst, const void* src) {
    asm volatile("cp.async.cg.shared.global [%0], [%1], 16;"
                 :: "r"(dst), "l"(src) : "memory");
}
#define CP_COMMIT() asm volatile("cp.async.commit_group;" ::: "memory")
#define CP_WAIT(n)  asm volatile("cp.async.wait_group %0;" :: "n"(n) : "memory")

__device__ __forceinline__ void ldm_x4(uint32_t* r, uint32_t addr) {
    asm volatile("ldmatrix.sync.aligned.m8n8.x4.shared.b16 {%0,%1,%2,%3}, [%4];"
        : "=r"(r[0]), "=r"(r[1]), "=r"(r[2]), "=r"(r[3]) : "r"(addr));
}

__device__ __forceinline__ void mma_bf16(float* c, const uint32_t* a, const uint32_t* b) {
    asm volatile(
        "mma.sync.aligned.m16n8k16.row.col.f32.bf16.bf16.f32 "
        "{%0,%1,%2,%3}, {%4,%5,%6,%7}, {%8,%9}, {%0,%1,%2,%3};"
        : "+f"(c[0]), "+f"(c[1]), "+f"(c[2]), "+f"(c[3])
        : "r"(a[0]), "r"(a[1]), "r"(a[2]), "r"(a[3]), "r"(b[0]), "r"(b[1]));
}

__device__ __forceinline__ uint2 cvt_f4_bf4(float4 v) {
    __nv_bfloat162 lo = __floats2bfloat162_rn(v.x, v.y);
    __nv_bfloat162 hi = __floats2bfloat162_rn(v.z, v.w);
    uint2 u;
    u.x = *reinterpret_cast<unsigned int*>(&lo);
    u.y = *reinterpret_cast<unsigned int*>(&hi);
    return u;
}

// ============================================================================
// Kernel 0 (merged): blocks [0,1024)      = per-leaf softmax (row in regs)
//                    blocks [1024,2048)   = X fp32 -> bf16 convert (MLP=8)
// Control resubmission: byte-equivalent to the configuration that measured
// 35.328us in Round 14.
// ============================================================================
__global__ void __launch_bounds__(128) prep_kernel(const float* __restrict__ X,
                                                   const float* __restrict__ logits) {
    const int bid = blockIdx.x;
    const int tid = threadIdx.x;

    if (bid >= NLEAF) {
        const int cb = bid - NLEAF;                   // 0..1023
        const float4* x4 = (const float4*)X;
        uint2* o = (uint2*)g_Xbf;
        const int base = cb * 128 + tid;              // 0..131071
        const int S = CVT_BLOCKS * 128;               // 131072 (n4 = 1048576)
        // ---- 8 independent loads, all issued before first use ----
        float4 v0 = __ldcs(&x4[base]);
        float4 v1 = __ldcs(&x4[base + S]);
        float4 v2 = __ldcs(&x4[base + 2 * S]);
        float4 v3 = __ldcs(&x4[base + 3 * S]);
        float4 v4 = __ldcs(&x4[base + 4 * S]);
        float4 v5 = __ldcs(&x4[base + 5 * S]);
        float4 v6 = __ldcs(&x4[base + 6 * S]);
        float4 v7 = __ldcs(&x4[base + 7 * S]);
        o[base]         = cvt_f4_bf4(v0);
        o[base + S]     = cvt_f4_bf4(v1);
        o[base + 2 * S] = cvt_f4_bf4(v2);
        o[base + 3 * S] = cvt_f4_bf4(v3);
        o[base + 4 * S] = cvt_f4_bf4(v4);
        o[base + 5 * S] = cvt_f4_bf4(v5);
        o[base + 6 * S] = cvt_f4_bf4(v6);
        o[base + 7 * S] = cvt_f4_bf4(v7);
        return;
    }

    // ---- softmax over 513 atoms for leaf `bid`, row cached in registers ----
    const int l = bid;
    const float* row = logits + (size_t)l * ATOMS;
    __shared__ float red_m[4];
    __shared__ float red_s[4];

    float v[4];
    #pragma unroll
    for (int j = 0; j < 4; j++) v[j] = row[tid + j * 128];   // 0..511
    const float vx = (tid == 0) ? row[512] : -1e30f;          // atom 512

    float m = fmaxf(fmaxf(v[0], v[1]), fmaxf(v[2], v[3]));
    m = fmaxf(m, vx);
    #pragma unroll
    for (int o = 16; o; o >>= 1) m = fmaxf(m, __shfl_xor_sync(~0u, m, o));
    if ((tid & 31) == 0) red_m[tid >> 5] = m;
    __syncthreads();
    m = fmaxf(fmaxf(red_m[0], red_m[1]), fmaxf(red_m[2], red_m[3]));

    float e[4];
    float s = 0.f;
    #pragma unroll
    for (int j = 0; j < 4; j++) { e[j] = __expf(v[j] - m); s += e[j]; }
    const float ex = (tid == 0) ? __expf(vx - m) : 0.f;
    s += ex;
    #pragma unroll
    for (int o = 16; o; o >>= 1) s += __shfl_xor_sync(~0u, s, o);
    if ((tid & 31) == 0) red_s[tid >> 5] = s;
    __syncthreads();
    s = red_s[0] + red_s[1] + red_s[2] + red_s[3];
    const float inv = 1.0f / s;

    __nv_bfloat16* W = g_Wbf + (size_t)l * NFEAT;
    #pragma unroll
    for (int j = 0; j < 4; j++) {
        const int k = tid + j * 128;
        const float w = e[j] * inv;
        if (k == 0) g_bias[l] = w;
        else        W[k - 1] = __float2bfloat16(w);
    }
    if (tid == 0) W[511] = __float2bfloat16(ex * inv);        // atom 512
}

// ============================================================================
// Kernel 1: bf16 mma.sync GEMM 128x128xK512, 3-stage cp.async pipeline,
//           fused bias + exp + row sum-exp
// grid = (BATCH/128, NLEAF/128), 256 threads (8 warps as 4 x 2)
// ============================================================================
__global__ void __launch_bounds__(256, 2) gemm_lse_kernel() {
    extern __shared__ __align__(16) char smem[];
    uint32_t sb = smem_to_u32(smem);
    const int tid = threadIdx.x;
    const int lid = tid & 31;
    const int wid = tid >> 5;
    const int warpM = wid >> 1;     // 0..3  (32 rows each)
    const int warpN = wid & 1;      // 0..1  (64 cols each)
    const int m0 = blockIdx.x * MT;
    const int n0 = blockIdx.y * NT;

    float* bias_s = (float*)(smem + SM_BIAS);
    float* rs     = (float*)(smem + SM_RS);
    for (int i = tid; i < NT; i += 256) bias_s[i] = g_bias[n0 + i];

    const char* Asrc = (const char*)(g_Xbf + (size_t)m0 * NFEAT);
    const char* Bsrc = (const char*)(g_Wbf + (size_t)n0 * NFEAT);

    auto load_tile = [&](int kt, int stage) {
        uint32_t abase = sb + SM_A + stage * STAGE_BYTES;
        uint32_t bbase = sb + SM_B + stage * STAGE_BYTES;
        #pragma unroll
        for (int i = 0; i < 4; i++) {
            int idx = tid + i * 256;         // 0..1023
            int row = idx >> 3, j = idx & 7;
            uint32_t sw = SMEM_SWIZZLE_128B((uint32_t)(row * 128 + j * 16));
            const size_t gsrc = ((size_t)row * NFEAT + (size_t)kt * KT) * 2 + j * 16;
            cp_async16(abase + sw, Asrc + gsrc);
            cp_async16(bbase + sw, Bsrc + gsrc);
        }
    };

    // ldmatrix per-lane pre-swizzle byte offsets
    const uint32_t a_off0 = (uint32_t)((warpM * 32 +  0 + (lid & 15)) * 128 + ((lid >> 4) << 4));
    const uint32_t a_off1 = (uint32_t)((warpM * 32 + 16 + (lid & 15)) * 128 + ((lid >> 4) << 4));
    const int b_nrow = (lid & 7) + ((lid >> 4) << 3);
    const uint32_t b_off = (uint32_t)((warpN * 64 + b_nrow) * 128 + (((lid >> 3) & 1) << 4));

    float acc[2][8][4];
    #pragma unroll
    for (int m = 0; m < 2; m++)
        #pragma unroll
        for (int nf = 0; nf < 8; nf++)
            #pragma unroll
            for (int c = 0; c < 4; c++) acc[m][nf][c] = 0.f;

    // Prologue: stages 0,1 in flight
    load_tile(0, 0);
    CP_COMMIT();
    load_tile(1, 1);
    CP_COMMIT();

    int stage = 0;
    for (int kt = 0; kt < NKT; kt++) {
        CP_WAIT(1);                // stage kt's group complete (groups retire in order)
        __syncthreads();           // visibility + WAR guard for stage (kt+2)%3

        if (kt + 2 < NKT) load_tile(kt + 2, (stage + 2 >= STAGES) ? stage + 2 - STAGES : stage + 2);
        CP_COMMIT();               // exactly one group per iteration (may be empty)

        const uint32_t abase = sb + SM_A + stage * STAGE_BYTES;
        const uint32_t bbase = sb + SM_B + stage * STAGE_BYTES;

        #pragma unroll
        for (int ks = 0; ks < 4; ks++) {     // 4 x k16 = KT
            uint32_t a[2][4];
            ldm_x4(a[0], abase + SMEM_SWIZZLE_128B(a_off0 + ks * 32));
            ldm_x4(a[1], abase + SMEM_SWIZZLE_128B(a_off1 + ks * 32));
            #pragma unroll
            for (int p = 0; p < 4; p++) {    // 4 x (2 n-octets) = 64 cols
                uint32_t b[4];
                ldm_x4(b, bbase + SMEM_SWIZZLE_128B(b_off + p * 2048 + ks * 32));
                mma_bf16(acc[0][2 * p],     a[0], b);
                mma_bf16(acc[0][2 * p + 1], a[0], b + 2);
                mma_bf16(acc[1][2 * p],     a[1], b);
                mma_bf16(acc[1][2 * p + 1], a[1], b + 2);
            }
        }
        stage = (stage + 1 >= STAGES) ? 0 : stage + 1;
    }

    // Fused epilogue: exp(acc + bias), reduce rows deterministically
    const int g  = lid >> 2;
    const int tg = lid & 3;
    #pragma unroll
    for (int m = 0; m < 2; m++) {
        #pragma unroll
        for (int h = 0; h < 2; h++) {        // h=0: rows g, h=1: rows g+8
            float s = 0.f;
            #pragma unroll
            for (int nf = 0; nf < 8; nf++) {
                const int col = warpN * 64 + nf * 8 + tg * 2;
                s += __expf(acc[m][nf][2 * h]     + bias_s[col]);
                s += __expf(acc[m][nf][2 * h + 1] + bias_s[col + 1]);
            }
            s += __shfl_xor_sync(~0u, s, 1);
            s += __shfl_xor_sync(~0u, s, 2);
            if (tg == 0) {
                const int row = warpM * 32 + m * 16 + h * 8 + g;
                rs[row * 2 + warpN] = s;
            }
        }
    }
    __syncthreads();
    if (tid < MT) {
        // row-major partials: [row][tile] -> finalize reads 2 contiguous float4
        g_part[(size_t)(m0 + tid) * NTILES + blockIdx.y] = rs[tid * 2] + rs[tid * 2 + 1];
    }
}

// ============================================================================
// Kernel 2: combine the 8 contiguous per-row partials, final log
// ============================================================================
__global__ void __launch_bounds__(256) finalize_kernel(float* __restrict__ out) {
    int i = blockIdx.x * blockDim.x + threadIdx.x;
    if (i < BATCH) {
        const float4* p = (const float4*)g_part;
        float4 a = p[i * 2];
        float4 b = p[i * 2 + 1];
        out[i] = logf((a.x + a.y + a.z + a.w) + (b.x + b.y + b.z + b.w));
    }
}

// ============================================================================
// Launch
// ============================================================================
extern "C" void kernel_launch(void* const* d_in, const int* in_sizes, int n_in,
                              void* d_out, int out_size) {
    const float* X      = (const float*)d_in[0];   // (8192, 512) f32
    const float* logits = (const float*)d_in[1];   // (1024, 513) f32
    float* out          = (float*)d_out;           // (8192,) f32

    cudaFuncSetAttribute(gemm_lse_kernel,
                         cudaFuncAttributeMaxDynamicSharedMemorySize, SMEM_TOTAL);

    prep_kernel<<<NLEAF + CVT_BLOCKS, 128>>>(X, logits);  // 1024 softmax + 1024 convert
    gemm_lse_kernel<<<dim3(BATCH / MT, NLEAF / NT), 256, SMEM_TOTAL>>>();
    finalize_kernel<<<BATCH / 256, 256>>>(out);
}